// round 6
// baseline (speedup 1.0000x reference)
#include <cuda_runtime.h>
#include <cuda_bf16.h>
#include <cstddef>

// x[64,512,128] @ Wx[128,1024] + b -> XP (in d_out); then
// h_t = tanh(xp_t + h_{t-1} @ Wh[1024,1024]); out[b,t,:] = h_t.
#define BB 64
#define TT 512
#define DD 128
#define HH 1024

typedef unsigned long long ull;

__device__ __forceinline__ ull pk2(float lo, float hi) {
    ull r; asm("mov.b64 %0, {%1, %2};" : "=l"(r) : "f"(lo), "f"(hi)); return r;
}
__device__ __forceinline__ float2 upk2(ull v) {
    float lo, hi; asm("mov.b64 {%0, %1}, %2;" : "=f"(lo), "=f"(hi) : "l"(v));
    return make_float2(lo, hi);
}
__device__ __forceinline__ ull ffma2(ull a, ull b, ull c) {
    ull d; asm("fma.rn.f32x2 %0, %1, %2, %3;" : "=l"(d) : "l"(a), "l"(b), "l"(c));
    return d;
}
__device__ __forceinline__ int ld_acq(const int* p) {
    int v; asm volatile("ld.acquire.gpu.global.s32 %0, [%1];" : "=r"(v) : "l"(p));
    return v;
}
__device__ __forceinline__ void red_rel_add1(int* p) {
    asm volatile("red.release.gpu.global.add.s32 [%0], 1;" :: "l"(p) : "memory");
}
__device__ __forceinline__ unsigned smem_u32(const void* p) {
    unsigned a;
    asm("{ .reg .u64 t; cvta.to.shared.u64 t, %1; cvt.u32.u64 %0, t; }"
        : "=r"(a) : "l"(p));
    return a;
}
__device__ __forceinline__ void mbar_init(unsigned a, int cnt) {
    asm volatile("mbarrier.init.shared.b64 [%0], %1;" :: "r"(a), "r"(cnt) : "memory");
}
__device__ __forceinline__ void mbar_arrive(unsigned a) {
    asm volatile("mbarrier.arrive.shared.b64 _, [%0];" :: "r"(a) : "memory");
}
__device__ __forceinline__ void mbar_wait(unsigned a, unsigned parity) {
    asm volatile(
        "{\n\t"
        ".reg .pred P;\n\t"
        "WAIT_%=:\n\t"
        "mbarrier.try_wait.parity.acquire.cta.shared::cta.b64 P, [%0], %1, 0x989680;\n\t"
        "@P bra.uni DONE_%=;\n\t"
        "bra.uni WAIT_%=;\n\t"
        "DONE_%=:\n\t"
        "}"
        :: "r"(a), "r"(parity) : "memory");
}
// fast tanh: exp-based, ~1e-6 rel err; clamp avoids inf/inf.
__device__ __forceinline__ float fast_tanh(float x) {
    x = fminf(fmaxf(x, -15.f), 15.f);
    float e = __expf(x + x);
    return __fdividef(e - 1.f, e + 1.f);
}

// ---------- global scratch ----------
__device__ float g_h[2][BB][HH];         // h double buffer, row-major [b][k]
__device__ int   g_flags[4][TT][8];      // (group, step, k-chunk) warp arrivals

// =====================================================================
// Kernel 1: XP = x @ Wx + b  -> d_out   (M=32768, K=128, N=1024)
// Block (0,0) also resets the step flags.
// =====================================================================
__global__ __launch_bounds__(256) void xp_gemm(
    const float* __restrict__ x, const float* __restrict__ Wx,
    const float* __restrict__ bias, float* __restrict__ out)
{
    __shared__ float xs[64 * 68];
    __shared__ float ws[64 * 64];

    const int tid = threadIdx.x;
    if (blockIdx.x == 0 && blockIdx.y == 0) {
        int* f = &g_flags[0][0][0];
        #pragma unroll
        for (int i = tid; i < 4 * TT * 8; i += 256) f[i] = 0;
    }

    const int m0 = blockIdx.x * 64;
    const int n0 = blockIdx.y * 64;
    const int ty = tid >> 4;
    const int tx = tid & 15;

    ull acc01[4] = {0ull, 0ull, 0ull, 0ull};
    ull acc23[4] = {0ull, 0ull, 0ull, 0ull};

    for (int k0 = 0; k0 < DD; k0 += 64) {
        __syncthreads();
        #pragma unroll
        for (int i = tid; i < 1024; i += 256) {
            int r = i >> 4, q = i & 15;
            ((float4*)xs)[r * 17 + q] =
                *(const float4*)&x[(size_t)(m0 + r) * DD + k0 + 4 * q];
        }
        #pragma unroll
        for (int i = tid; i < 1024; i += 256) {
            int r = i >> 4, q = i & 15;
            ((float4*)ws)[i] =
                *(const float4*)&Wx[(size_t)(k0 + r) * HH + n0 + 4 * q];
        }
        __syncthreads();

        #pragma unroll 8
        for (int kk = 0; kk < 64; kk++) {
            ulonglong2 wv = *(const ulonglong2*)&ws[kk * 64 + 4 * tx];
            #pragma unroll
            for (int i = 0; i < 4; i++) {
                float a = xs[(4 * ty + i) * 68 + kk];
                ull aa = pk2(a, a);
                acc01[i] = ffma2(aa, wv.x, acc01[i]);
                acc23[i] = ffma2(aa, wv.y, acc23[i]);
            }
        }
    }

    float4 bv = *(const float4*)&bias[n0 + 4 * tx];
    #pragma unroll
    for (int i = 0; i < 4; i++) {
        float2 p0 = upk2(acc01[i]);
        float2 p1 = upk2(acc23[i]);
        float4 r;
        r.x = p0.x + bv.x; r.y = p0.y + bv.y;
        r.z = p1.x + bv.z; r.w = p1.y + bv.w;
        *(float4*)&out[(size_t)(m0 + 4 * ty + i) * HH + n0 + 4 * tx] = r;
    }
}

// =====================================================================
// Kernel 2: persistent recurrence, barrier-free steps.
// 128 CTAs, 256 thr (8 warps). CTA (g,j): batches [16g,16g+16),
// cols [32j,32j+32), produces k-chunk j>>2.
// Warp ks consumes chunk ks; lane (cq=lane&7, bq=lane>>3) -> 4b x 4c tile.
// SMEM:
//   wb4[256][32] float4 : Wh K-blocked, col c at slot (c&3)*8+(c>>2)
//   hb4 alternating-stride rows (offset(k4)=(33*k4)>>1 float4), batch b at
//       slot (b&3)*4+(b>>2)
//   red[2][8][16][32] float : parity-double-buffered k-split partials
//   mbarP[2], mbarE[2] : 8-arrival mbarriers (produce-join, epilogue-done)
// No __syncthreads in the step loop: warps free-run across steps.
// =====================================================================
#define WB4_F4   8192                    /* 256*32 */
#define HB4_F4   4224                    /* sum of alternating 16/17 rows */
#define SMEM_BYTES (WB4_F4*16 + HB4_F4*16 + 2*8*16*32*4 + 32)

__global__ __launch_bounds__(256) void rnn_persist(
    float* __restrict__ out, const float* __restrict__ Wh)
{
    extern __shared__ float4 sm4[];
    float4* wb4 = sm4;                          // [256][32]
    float4* hb4 = sm4 + WB4_F4;                 // 4224 float4
    float*  red = (float*)(sm4 + WB4_F4 + HB4_F4);  // [2][8][16][32]
    ull*    mb  = (ull*)(red + 2 * 8 * 16 * 32);    // mbarP[2], mbarE[2]

    const int tid = threadIdx.x;
    const int g   = blockIdx.x >> 5;
    const int j   = blockIdx.x & 31;
    const int B0  = 16 * g;
    const int C0  = 32 * j;
    const int jc  = j >> 2;

    if (tid == 0) {
        mbar_init(smem_u32(&mb[0]), 8);
        mbar_init(smem_u32(&mb[1]), 8);
        mbar_init(smem_u32(&mb[2]), 8);
        mbar_init(smem_u32(&mb[3]), 8);
    }

    // one-time: Wh slice, K-transposed into float4 blocks, permuted col slots
    for (int idx = tid; idx < 8192; idx += 256) {
        int k4 = idx >> 5, c = idx & 31;
        const float* p = &Wh[(size_t)(4 * k4) * HH + C0 + c];
        float4 v;
        v.x = p[0]; v.y = p[HH]; v.z = p[2 * HH]; v.w = p[3 * HH];
        wb4[k4 * 32 + ((c & 3) * 8 + (c >> 2))] = v;
    }
    __syncthreads();   // covers wb4 + mbarrier init

    const int ks   = tid >> 5;
    const int lane = tid & 31;
    const int cq   = lane & 7;
    const int bq   = lane >> 3;

    // epilogue mapping: warp ks publishes batches 2ks, 2ks+1
    const int eb  = 2 * ks + (lane >> 4);     // local batch
    const int ec2 = 2 * (lane & 15);          // col offset

    const unsigned mbP0 = smem_u32(&mb[0]);
    const unsigned mbE0 = smem_u32(&mb[2]);

    for (int t = 0; t < TT; t++) {
        const int p = t & 1;
        const unsigned mP = mbP0 + 8 * p;
        const unsigned mE = mbE0 + 8 * p;
        float* redp = red + p * (8 * 16 * 32);

        // prefetch xp for this warp's epilogue slice
        size_t ob = ((size_t)(B0 + eb) * TT + t) * HH + C0 + ec2;
        float2 xp = __ldcg((const float2*)&out[ob]);

        if (t > 0) {
            // wait for this chunk's 4 producer CTAs (32 warp-arrivals)
            int* myflag = &g_flags[g][t - 1][ks];
            while (ld_acq(myflag) < 32) { }

            // stage this warp's 128-k chunk of h_{t-1}
            const float4* src = (const float4*)&g_h[p ^ 1][B0][0]; // [16][256]
            const int k4r = 32 * ks + lane;
            const int hoff = (33 * k4r) >> 1;
            #pragma unroll
            for (int b = 0; b < 16; b++) {
                float4 v = __ldcg(src + b * 256 + k4r);
                hb4[hoff + ((b & 3) * 4 + (b >> 2))] = v;
            }
            __syncwarp();

            // ensure red[p] free (epilogue of step t-2 done) — usually instant
            if (t >= 2) mbar_wait(mE, ((t >> 1) + 1) & 1);

            // compute 32 k4 (16 pairs); both operand LDS are 1-wavefront
            const float4* wp  = wb4 + (32 * ks) * 32 + cq;
            const float4* hpE = hb4 + 528 * ks + bq;
            ull a[4][4];
            #pragma unroll
            for (int bi = 0; bi < 4; bi++)
                #pragma unroll
                for (int ci = 0; ci < 4; ci++) a[bi][ci] = 0ull;

            #pragma unroll 4
            for (int m = 0; m < 16; m++) {
                ulonglong2 wv[4], hv[4];
                #pragma unroll
                for (int i = 0; i < 4; i++)
                    wv[i] = *(const ulonglong2*)(wp + 8 * i);
                #pragma unroll
                for (int i = 0; i < 4; i++)
                    hv[i] = *(const ulonglong2*)(hpE + 4 * i);
                #pragma unroll
                for (int bi = 0; bi < 4; bi++)
                    #pragma unroll
                    for (int ci = 0; ci < 4; ci++) {
                        a[bi][ci] = ffma2(hv[bi].x, wv[ci].x, a[bi][ci]);
                        a[bi][ci] = ffma2(hv[bi].y, wv[ci].y, a[bi][ci]);
                    }
                #pragma unroll
                for (int i = 0; i < 4; i++)
                    wv[i] = *(const ulonglong2*)(wp + 32 + 8 * i);
                #pragma unroll
                for (int i = 0; i < 4; i++)
                    hv[i] = *(const ulonglong2*)(hpE + 16 + 4 * i);
                #pragma unroll
                for (int bi = 0; bi < 4; bi++)
                    #pragma unroll
                    for (int ci = 0; ci < 4; ci++) {
                        a[bi][ci] = ffma2(hv[bi].x, wv[ci].x, a[bi][ci]);
                        a[bi][ci] = ffma2(hv[bi].y, wv[ci].y, a[bi][ci]);
                    }
                wp += 64; hpE += 33;
            }

            // horizontal add -> red[p][ks][b][c]
            #pragma unroll
            for (int bi = 0; bi < 4; bi++) {
                float2 v0 = upk2(a[bi][0]);
                float2 v1 = upk2(a[bi][1]);
                float2 v2 = upk2(a[bi][2]);
                float2 v3 = upk2(a[bi][3]);
                float4 r4;
                r4.x = v0.x + v0.y; r4.y = v1.x + v1.y;
                r4.z = v2.x + v2.y; r4.w = v3.x + v3.y;
                *(float4*)&redp[(ks * 16 + 4 * bq + bi) * 32 + 4 * cq] = r4;
            }
            __syncwarp();
        } else if (t >= 2) {
            mbar_wait(mE, ((t >> 1) + 1) & 1);
        }

        if (lane == 0) mbar_arrive(mP);
        mbar_wait(mP, (t >> 1) & 1);    // join: all 8 producers done

        // epilogue: this warp's 2 batches x 32 cols
        float sx = xp.x, sy = xp.y;
        if (t > 0) {
            #pragma unroll
            for (int s = 0; s < 8; s++) {
                float2 rv = *(const float2*)&redp[(s * 16 + eb) * 32 + ec2];
                sx += rv.x; sy += rv.y;
            }
        }
        float rx = fast_tanh(sx), ry = fast_tanh(sy);
        *(float2*)&g_h[p][B0 + eb][C0 + ec2] = make_float2(rx, ry);
        __syncwarp();
        if (lane == 0) red_rel_add1(&g_flags[g][t][jc]);
        *(float2*)&out[ob] = make_float2(rx, ry);   // off critical path

        if (lane == 0) mbar_arrive(mE);   // red[p] consumed by this warp
    }
}

// =====================================================================
// Launch
// =====================================================================
extern "C" void kernel_launch(void* const* d_in, const int* in_sizes, int n_in,
                              void* d_out, int out_size)
{
    const float* x  = nullptr;
    const float* Wx = nullptr;
    const float* Wh = nullptr;
    const float* bv = nullptr;
    for (int i = 0; i < n_in; i++) {
        int s = in_sizes[i];
        if (s == BB * TT * DD)      x  = (const float*)d_in[i];
        else if (s == DD * HH)      Wx = (const float*)d_in[i];
        else if (s == HH * HH)      Wh = (const float*)d_in[i];
        else if (s == HH)           bv = (const float*)d_in[i];
    }
    float* out = (float*)d_out;

    static int configured = 0;
    if (!configured) {
        cudaFuncSetAttribute(rnn_persist,
                             cudaFuncAttributeMaxDynamicSharedMemorySize,
                             SMEM_BYTES);
        configured = 1;
    }

    dim3 g1((BB * TT) / 64, HH / 64);
    xp_gemm<<<g1, 256>>>(x, Wx, bv, out);

    rnn_persist<<<128, 256, SMEM_BYTES>>>(out, Wh);
}

// round 7
// speedup vs baseline: 1.0595x; 1.0595x over previous
#include <cuda_runtime.h>
#include <cuda_bf16.h>
#include <cstddef>

// x[64,512,128] @ Wx[128,1024] + b -> XP (in d_out); then
// h_t = tanh(xp_t + h_{t-1} @ Wh[1024,1024]); out[b,t,:] = h_t.
#define BB 64
#define TT 512
#define DD 128
#define HH 1024

typedef unsigned long long ull;

__device__ __forceinline__ ull pk2(float lo, float hi) {
    ull r; asm("mov.b64 %0, {%1, %2};" : "=l"(r) : "f"(lo), "f"(hi)); return r;
}
__device__ __forceinline__ float2 upk2(ull v) {
    float lo, hi; asm("mov.b64 {%0, %1}, %2;" : "=f"(lo), "=f"(hi) : "l"(v));
    return make_float2(lo, hi);
}
__device__ __forceinline__ ull ffma2(ull a, ull b, ull c) {
    ull d; asm("fma.rn.f32x2 %0, %1, %2, %3;" : "=l"(d) : "l"(a), "l"(b), "l"(c));
    return d;
}
__device__ __forceinline__ int ld_acq(const int* p) {
    int v; asm volatile("ld.acquire.gpu.global.s32 %0, [%1];" : "=r"(v) : "l"(p));
    return v;
}
__device__ __forceinline__ void red_rel_add1(int* p) {
    asm volatile("red.release.gpu.global.add.s32 [%0], 1;" :: "l"(p) : "memory");
}
// fast tanh: exp-based, ~1e-6 rel err; clamp avoids inf/inf.
__device__ __forceinline__ float fast_tanh(float x) {
    x = fminf(fmaxf(x, -15.f), 15.f);
    float e = __expf(x + x);
    return __fdividef(e - 1.f, e + 1.f);
}

// ---------- global scratch ----------
__device__ float g_h[2][BB][HH];         // h double buffer, row-major [b][k]
__device__ int   g_flags[4][TT][8];      // (group, step, k-chunk) warp arrivals

// =====================================================================
// Kernel 1: XP = x @ Wx + b  -> d_out   (M=32768, K=128, N=1024)
// Block (0,0) also resets the step flags.
// =====================================================================
__global__ __launch_bounds__(256) void xp_gemm(
    const float* __restrict__ x, const float* __restrict__ Wx,
    const float* __restrict__ bias, float* __restrict__ out)
{
    __shared__ float xs[64 * 68];
    __shared__ float ws[64 * 64];

    const int tid = threadIdx.x;
    if (blockIdx.x == 0 && blockIdx.y == 0) {
        int* f = &g_flags[0][0][0];
        #pragma unroll
        for (int i = tid; i < 4 * TT * 8; i += 256) f[i] = 0;
    }

    const int m0 = blockIdx.x * 64;
    const int n0 = blockIdx.y * 64;
    const int ty = tid >> 4;
    const int tx = tid & 15;

    ull acc01[4] = {0ull, 0ull, 0ull, 0ull};
    ull acc23[4] = {0ull, 0ull, 0ull, 0ull};

    for (int k0 = 0; k0 < DD; k0 += 64) {
        __syncthreads();
        #pragma unroll
        for (int i = tid; i < 1024; i += 256) {
            int r = i >> 4, q = i & 15;
            ((float4*)xs)[r * 17 + q] =
                *(const float4*)&x[(size_t)(m0 + r) * DD + k0 + 4 * q];
        }
        #pragma unroll
        for (int i = tid; i < 1024; i += 256) {
            int r = i >> 4, q = i & 15;
            ((float4*)ws)[i] =
                *(const float4*)&Wx[(size_t)(k0 + r) * HH + n0 + 4 * q];
        }
        __syncthreads();

        #pragma unroll 8
        for (int kk = 0; kk < 64; kk++) {
            ulonglong2 wv = *(const ulonglong2*)&ws[kk * 64 + 4 * tx];
            #pragma unroll
            for (int i = 0; i < 4; i++) {
                float a = xs[(4 * ty + i) * 68 + kk];
                ull aa = pk2(a, a);
                acc01[i] = ffma2(aa, wv.x, acc01[i]);
                acc23[i] = ffma2(aa, wv.y, acc23[i]);
            }
        }
    }

    float4 bv = *(const float4*)&bias[n0 + 4 * tx];
    #pragma unroll
    for (int i = 0; i < 4; i++) {
        float2 p0 = upk2(acc01[i]);
        float2 p1 = upk2(acc23[i]);
        float4 r;
        r.x = p0.x + bv.x; r.y = p0.y + bv.y;
        r.z = p1.x + bv.z; r.w = p1.y + bv.w;
        *(float4*)&out[(size_t)(m0 + 4 * ty + i) * HH + n0 + 4 * tx] = r;
    }
}

// =====================================================================
// Kernel 2: persistent recurrence. 128 CTAs (1/SM), 512 thr (16 warps).
// CTA (g,j): batches [16g,16g+16), cols [32j,32j+32); produces chunk j>>2.
// Warp w consumes k4 in [16w,16w+16) (64 k) = half of chunk w>>1.
// Lane tile (cq=lane&7, bq=lane>>3): 4 batches x 4 cols, packed-over-k.
// SMEM:
//   wb4[256][32] float4 : Wh K-blocked, col c at slot (c&3)*8+(c>>2)
//   hb4 alternating rows (offset(k4)=(33*k4)>>1), batch b at (b&3)*4+(b>>2)
//   red[16][16][32] float : 16 k-split partials
// Epilogue: warp w publishes batch w across 32 cols (coalesced floats).
// Flags target 64 = 4 producer CTAs x 16 warps.
// =====================================================================
#define WB4_F4   8192                    /* 256*32 float4 = 128KB */
#define HB4_F4   4224                    /* alternating 16/17 rows = 66KB */
#define RED_F    (16 * 16 * 32)          /* 32KB */
#define SMEM_BYTES (WB4_F4 * 16 + HB4_F4 * 16 + RED_F * 4)  /* 231,424 */

__global__ __launch_bounds__(512) void rnn_persist(
    float* __restrict__ out, const float* __restrict__ Wh)
{
    extern __shared__ float4 sm4[];
    float4* wb4 = sm4;                        // [256][32]
    float4* hb4 = sm4 + WB4_F4;               // 4224 float4
    float*  red = (float*)(sm4 + WB4_F4 + HB4_F4); // [16][16][32]

    const int tid = threadIdx.x;
    const int g   = blockIdx.x >> 5;
    const int j   = blockIdx.x & 31;
    const int B0  = 16 * g;
    const int C0  = 32 * j;
    const int jc  = j >> 2;                   // chunk this CTA produces

    // one-time: Wh slice, K-transposed into float4 blocks, permuted col slots
    for (int idx = tid; idx < 8192; idx += 512) {
        int k4 = idx >> 5, c = idx & 31;
        const float* p = &Wh[(size_t)(4 * k4) * HH + C0 + c];
        float4 v;
        v.x = p[0]; v.y = p[HH]; v.z = p[2 * HH]; v.w = p[3 * HH];
        wb4[k4 * 32 + ((c & 3) * 8 + (c >> 2))] = v;
    }
    __syncthreads();

    const int w    = tid >> 5;          // warp 0..15: k4 in [16w, 16w+16)
    const int lane = tid & 31;
    const int cq   = lane & 7;          // cols 4cq..4cq+3
    const int bq   = lane >> 3;         // batches 4bq..4bq+3
    const int kc   = w >> 1;            // chunk consumed (flags index)

    // staging mapping: lane -> (k4 within slice, batch half)
    const int sk4  = 16 * w + (lane & 15);
    const int sbh  = (lane >> 4) * 8;
    const int hoff = (33 * sk4) >> 1;

    // epilogue mapping: warp w -> batch w, lane -> col
    const size_t hrow = (size_t)(B0 + w) * TT;

    for (int t = 0; t < TT; t++) {
        const int p = t & 1;

        // prefetch xp for this thread's epilogue element
        size_t ob = (hrow + t) * HH + C0 + lane;
        float xp = __ldcg(&out[ob]);

        if (t > 0) {
            // wait for this chunk's 4 producer CTAs (64 warp-arrivals)
            int* myflag = &g_flags[g][t - 1][kc];
            while (ld_acq(myflag) < 64) { }

            // stage this warp's 64-k slice of h_{t-1} (8 loads/lane)
            const float4* src = (const float4*)&g_h[p ^ 1][B0][0]; // [16][256]
            #pragma unroll
            for (int i = 0; i < 8; i++) {
                int b = sbh + i;
                float4 v = __ldcg(src + b * 256 + sk4);
                hb4[hoff + ((b & 3) * 4 + (b >> 2))] = v;
            }
            __syncwarp();

            // compute 16 k4 = 8 pairs; all LDS one-wavefront
            const float4* wp  = wb4 + (16 * w) * 32 + cq;
            const float4* hpE = hb4 + 264 * w + bq;
            ull a[4][4];
            #pragma unroll
            for (int bi = 0; bi < 4; bi++)
                #pragma unroll
                for (int ci = 0; ci < 4; ci++) a[bi][ci] = 0ull;

            #pragma unroll
            for (int m = 0; m < 8; m++) {
                ulonglong2 wv[4], hv[4];
                #pragma unroll
                for (int i = 0; i < 4; i++)
                    wv[i] = *(const ulonglong2*)(wp + 8 * i);
                #pragma unroll
                for (int i = 0; i < 4; i++)
                    hv[i] = *(const ulonglong2*)(hpE + 4 * i);
                #pragma unroll
                for (int bi = 0; bi < 4; bi++)
                    #pragma unroll
                    for (int ci = 0; ci < 4; ci++) {
                        a[bi][ci] = ffma2(hv[bi].x, wv[ci].x, a[bi][ci]);
                        a[bi][ci] = ffma2(hv[bi].y, wv[ci].y, a[bi][ci]);
                    }
                #pragma unroll
                for (int i = 0; i < 4; i++)
                    wv[i] = *(const ulonglong2*)(wp + 32 + 8 * i);
                #pragma unroll
                for (int i = 0; i < 4; i++)
                    hv[i] = *(const ulonglong2*)(hpE + 16 + 4 * i);
                #pragma unroll
                for (int bi = 0; bi < 4; bi++)
                    #pragma unroll
                    for (int ci = 0; ci < 4; ci++) {
                        a[bi][ci] = ffma2(hv[bi].x, wv[ci].x, a[bi][ci]);
                        a[bi][ci] = ffma2(hv[bi].y, wv[ci].y, a[bi][ci]);
                    }
                wp += 64; hpE += 33;
            }

            // horizontal add -> red[w][b][c]
            #pragma unroll
            for (int bi = 0; bi < 4; bi++) {
                float2 v0 = upk2(a[bi][0]);
                float2 v1 = upk2(a[bi][1]);
                float2 v2 = upk2(a[bi][2]);
                float2 v3 = upk2(a[bi][3]);
                float4 r4;
                r4.x = v0.x + v0.y; r4.y = v1.x + v1.y;
                r4.z = v2.x + v2.y; r4.w = v3.x + v3.y;
                *(float4*)&red[(w * 16 + 4 * bq + bi) * 32 + 4 * cq] = r4;
            }
        }
        __syncthreads();   // join: all partials in red

        // epilogue: warp w -> batch w, lane -> col; reduce 16 splits
        float s = xp;
        if (t > 0) {
            #pragma unroll
            for (int q = 0; q < 16; q++)
                s += red[(q * 16 + w) * 32 + lane];
        }
        float r = fast_tanh(s);
        g_h[p][B0 + w][C0 + lane] = r;
        __syncwarp();
        if (lane == 0) red_rel_add1(&g_flags[g][t][jc]);
        out[ob] = r;                       // off critical path

        __syncthreads();   // red reuse hazard fence
    }
}

// =====================================================================
// Launch
// =====================================================================
extern "C" void kernel_launch(void* const* d_in, const int* in_sizes, int n_in,
                              void* d_out, int out_size)
{
    const float* x  = nullptr;
    const float* Wx = nullptr;
    const float* Wh = nullptr;
    const float* bv = nullptr;
    for (int i = 0; i < n_in; i++) {
        int s = in_sizes[i];
        if (s == BB * TT * DD)      x  = (const float*)d_in[i];
        else if (s == DD * HH)      Wx = (const float*)d_in[i];
        else if (s == HH * HH)      Wh = (const float*)d_in[i];
        else if (s == HH)           bv = (const float*)d_in[i];
    }
    float* out = (float*)d_out;

    static int configured = 0;
    if (!configured) {
        cudaFuncSetAttribute(rnn_persist,
                             cudaFuncAttributeMaxDynamicSharedMemorySize,
                             SMEM_BYTES);
        configured = 1;
    }

    dim3 g1((BB * TT) / 64, HH / 64);
    xp_gemm<<<g1, 256>>>(x, Wx, bv, out);

    rnn_persist<<<128, 512, SMEM_BYTES>>>(out, Wh);
}